// round 14
// baseline (speedup 1.0000x reference)
#include <cuda_runtime.h>
#include <cuda_bf16.h>
#include <cuda_fp16.h>
#include <cstdint>

// Problem constants
#define BATCH 4
#define TT 8
#define HH 64
#define WW 64
#define CC 256
#define NTOK (BATCH*TT*HH*WW)          // 131072 tokens
#define NHEAD 8
#define HD 32
#define NWIN 1024
#define QKV_N 768
#define HID 512
#define SCALE 0.17677669529663687f     // 1/sqrt(32)

// ---------------- scratch ----------------
__device__ __half g_xnh [NTOK * CC];
__device__ __half g_qkvh[NTOK * QKV_N];
__device__ __half g_atth[NTOK * CC];
__device__ __half g_hidh[NTOK * HID];
__device__ float  g_x   [NTOK * CC];
__device__ __half g_wh  [1048576];
__device__ __half g_bm  [2 * NHEAD * 128 * 128];   // bias matrices (block, head)

#define OFF_QKV1 0
#define OFF_PROJ1 196608
#define OFF_M1W1 262144
#define OFF_M1W2 393216
#define OFF_QKV2 524288
#define OFF_PROJ2 720896
#define OFF_M2W1 786432
#define OFF_M2W2 917504

// ---------------- fused f32 -> f16 convert for all 8 weight matrices ----------
struct CvtArgs {
    const float* src[8];
    int dstoff[8];
    int cum[9];
};
__global__ __launch_bounds__(256)
void cvt8_kernel(CvtArgs a, __half* __restrict__ dst)
{
    int gid = blockIdx.x * 256 + threadIdx.x;
    int seg = 0;
    #pragma unroll
    for (int s = 1; s < 8; s++) seg += (gid >= a.cum[s]);
    int local = gid - a.cum[seg];
    if (gid >= a.cum[8]) return;
    const float4 v = *((const float4*)a.src[seg] + local);
    __half2 p0 = __floats2half2_rn(v.x, v.y);
    __half2 p1 = __floats2half2_rn(v.z, v.w);
    *(uint2*)(dst + a.dstoff[seg] + local*4) =
        make_uint2(*(uint32_t*)&p0, *(uint32_t*)&p1);
}

// ---------------- bias-matrix precompute: B[h][i][j] = rpb[rel(i,j)*8+h] ------
__global__ __launch_bounds__(256)
void biasmat_kernel(const float* __restrict__ rpb, __half* __restrict__ dst)
{
    int head = blockIdx.x;
    for (int idx = threadIdx.x; idx < 128*128; idx += 256) {
        int i = idx >> 7, j = idx & 127;
        int ti = i >> 6, hi = (i >> 3) & 7, wi = i & 7;
        int tj = j >> 6, hj = (j >> 3) & 7, wj = j & 7;
        int rel = (ti - tj + 1)*225 + (hi - hj + 7)*15 + (wi - wj + 7);
        dst[head*128*128 + idx] = __float2half_rn(__ldg(rpb + rel*NHEAD + head));
    }
}

// ---------------- LayerNorm: one warp per token, fp16 out ----------------
__global__ __launch_bounds__(256)
void ln_kernel(const float* __restrict__ x, const float* __restrict__ g,
               const float* __restrict__ b, __half* __restrict__ out)
{
    int gw   = (blockIdx.x * blockDim.x + threadIdx.x) >> 5;
    int lane = threadIdx.x & 31;
    if (gw >= NTOK) return;
    const float4* row = (const float4*)(x + (size_t)gw * CC);
    float4 v0 = row[2*lane];
    float4 v1 = row[2*lane + 1];
    float s = v0.x+v0.y+v0.z+v0.w + v1.x+v1.y+v1.z+v1.w;
    float q = v0.x*v0.x+v0.y*v0.y+v0.z*v0.z+v0.w*v0.w
            + v1.x*v1.x+v1.y*v1.y+v1.z*v1.z+v1.w*v1.w;
    #pragma unroll
    for (int o = 16; o > 0; o >>= 1) {
        s += __shfl_xor_sync(0xffffffffu, s, o);
        q += __shfl_xor_sync(0xffffffffu, q, o);
    }
    float mean = s * (1.0f/256.0f);
    float var  = q * (1.0f/256.0f) - mean*mean;
    float rstd = rsqrtf(var + 1e-5f);
    const float4* g4 = (const float4*)g;
    const float4* b4 = (const float4*)b;
    float4 ga = g4[2*lane], gb2 = g4[2*lane + 1];
    float4 ba = b4[2*lane], bb2 = b4[2*lane + 1];
    __half2 h0 = __floats2half2_rn((v0.x-mean)*rstd*ga.x  + ba.x,
                                   (v0.y-mean)*rstd*ga.y  + ba.y);
    __half2 h1 = __floats2half2_rn((v0.z-mean)*rstd*ga.z  + ba.z,
                                   (v0.w-mean)*rstd*ga.w  + ba.w);
    __half2 h2 = __floats2half2_rn((v1.x-mean)*rstd*gb2.x + bb2.x,
                                   (v1.y-mean)*rstd*gb2.y + bb2.y);
    __half2 h3 = __floats2half2_rn((v1.z-mean)*rstd*gb2.z + bb2.z,
                                   (v1.w-mean)*rstd*gb2.w + bb2.w);
    uint4 pack = make_uint4(*(uint32_t*)&h0, *(uint32_t*)&h1,
                            *(uint32_t*)&h2, *(uint32_t*)&h3);
    ((uint4*)(out + (size_t)gw * CC))[lane] = pack;
}

// ---------------- shared MMA helpers ----------------
__device__ __forceinline__ void ldsm_x4(uint32_t* r, const __half* p) {
    uint32_t a = (uint32_t)__cvta_generic_to_shared(p);
    asm volatile("ldmatrix.sync.aligned.m8n8.x4.shared.b16 {%0,%1,%2,%3}, [%4];"
        : "=r"(r[0]), "=r"(r[1]), "=r"(r[2]), "=r"(r[3]) : "r"(a));
}
__device__ __forceinline__ void ldsm_x4t(uint32_t* r, const __half* p) {
    uint32_t a = (uint32_t)__cvta_generic_to_shared(p);
    asm volatile("ldmatrix.sync.aligned.m8n8.x4.trans.shared.b16 {%0,%1,%2,%3}, [%4];"
        : "=r"(r[0]), "=r"(r[1]), "=r"(r[2]), "=r"(r[3]) : "r"(a));
}
__device__ __forceinline__ void mma_f16(float* c, const uint32_t* a,
                                        uint32_t b0, uint32_t b1) {
    asm volatile(
        "mma.sync.aligned.m16n8k16.row.col.f32.f16.f16.f32 "
        "{%0,%1,%2,%3}, {%4,%5,%6,%7}, {%8,%9}, {%0,%1,%2,%3};"
        : "+f"(c[0]), "+f"(c[1]), "+f"(c[2]), "+f"(c[3])
        : "r"(a[0]), "r"(a[1]), "r"(a[2]), "r"(a[3]), "r"(b0), "r"(b1));
}
__device__ __forceinline__ uint32_t packh2(float x0, float x1) {
    __half2 p = __floats2half2_rn(x0, x1);
    return *(uint32_t*)&p;
}
__device__ __forceinline__ float gelu_exact(float x) {
    return 0.5f * x * (1.0f + erff(x * 0.7071067811865475f));
}
__device__ __forceinline__ void cpa16(const __half* g, __half* s) {
    uint32_t sa = (uint32_t)__cvta_generic_to_shared(s);
    asm volatile("cp.async.cg.shared.global [%0], [%1], 16;" :: "r"(sa), "l"(g));
}

// ---------------- persistent fp16 tensor-core GEMM (R11 config, frozen) -------
#define BM 128
#define BN 128
#define BK 32
#define NSTAGE 4
#define ASTR 40
#define BSTR 136
#define STAGE_H (BM*ASTR + BK*BSTR)
#define GSMEM_BYTES (NSTAGE * STAGE_H * 2)

template<int EPI>
__global__ __launch_bounds__(256, 2)
void hgemm_kernel(int M, int N, int K,
                  const __half* __restrict__ A,
                  const __half* __restrict__ B,
                  const float* __restrict__ bias,
                  const float* __restrict__ Res,
                  float* __restrict__ C,
                  __half* __restrict__ Ch)
{
    extern __shared__ __half smg[];
    __shared__ float sbias[128];

    int tid  = threadIdx.x;
    int bn   = blockIdx.x;
    int warp = tid >> 5, lane = tid & 31;
    int wm   = warp >> 1, wn = warp & 1;

    const __half* Bb = B + bn * BN;
    if (tid < 128) sbias[tid] = __ldg(bias + bn*BN + tid);

    int ar = tid >> 2, ac = (tid & 3) * 8;
    int br = tid >> 4, bc = (tid & 15) * 8;

    int MT = M >> 7;
    int ntiles = (MT - blockIdx.y + gridDim.y - 1) / gridDim.y;
    int nk = K / BK;
    int total = ntiles * nk;
    size_t rowStride = (size_t)gridDim.y * 128;

    float acc[2][8][4];
    #pragma unroll
    for (int i = 0; i < 2; i++)
        #pragma unroll
        for (int j = 0; j < 8; j++)
            #pragma unroll
            for (int k = 0; k < 4; k++) acc[i][j][k] = 0.0f;

    const __half* Aload = A + (size_t)blockIdx.y * 128 * K;
    int k_load = 0;

    #pragma unroll
    for (int s = 0; s < NSTAGE-1; s++) {
        __half* As = smg + s * STAGE_H;
        __half* Bs = As + BM*ASTR;
        int kcol = k_load * BK;
        cpa16(Aload + (size_t)ar * K + kcol + ac,        As + ar*ASTR + ac);
        cpa16(Aload + (size_t)(ar+64) * K + kcol + ac,   As + (ar+64)*ASTR + ac);
        cpa16(Bb + (size_t)(kcol + br) * N + bc,         Bs + br*BSTR + bc);
        cpa16(Bb + (size_t)(kcol + br + 16) * N + bc,    Bs + (br+16)*BSTR + bc);
        asm volatile("cp.async.commit_group;");
        k_load++;
    }

    int arow = wm*32 + (lane & 15);
    int aoff = (lane >> 4) * 8;
    int brow = lane & 15;
    int bcol = wn*64 + (lane >> 4) * 8;

    int kc = 0;
    size_t bmrow = (size_t)blockIdx.y * 128;

    for (int c = 0; c < total; c++) {
        asm volatile("cp.async.wait_group %0;" :: "n"(NSTAGE-2));
        __syncthreads();

        if (c + NSTAGE-1 < total) {
            __half* As = smg + ((c + NSTAGE-1) & (NSTAGE-1)) * STAGE_H;
            __half* Bs = As + BM*ASTR;
            int kcol = k_load * BK;
            cpa16(Aload + (size_t)ar * K + kcol + ac,        As + ar*ASTR + ac);
            cpa16(Aload + (size_t)(ar+64) * K + kcol + ac,   As + (ar+64)*ASTR + ac);
            cpa16(Bb + (size_t)(kcol + br) * N + bc,         Bs + br*BSTR + bc);
            cpa16(Bb + (size_t)(kcol + br + 16) * N + bc,    Bs + (br+16)*BSTR + bc);
            if (++k_load == nk) { k_load = 0; Aload += rowStride * K; }
        }
        asm volatile("cp.async.commit_group;");

        const __half* As = smg + (c & (NSTAGE-1)) * STAGE_H;
        const __half* Bs = As + BM*ASTR;

        #pragma unroll
        for (int kk = 0; kk < BK; kk += 16) {
            uint32_t af[2][4], bf[4][4];
            #pragma unroll
            for (int mf = 0; mf < 2; mf++)
                ldsm_x4(af[mf], As + (arow + mf*16)*ASTR + kk + aoff);
            #pragma unroll
            for (int gg = 0; gg < 4; gg++)
                ldsm_x4t(bf[gg], Bs + (kk + brow)*BSTR + bcol + gg*16);
            #pragma unroll
            for (int mf = 0; mf < 2; mf++)
                #pragma unroll
                for (int nf = 0; nf < 8; nf++)
                    mma_f16(acc[mf][nf], af[mf],
                            bf[nf>>1][(nf&1)*2], bf[nf>>1][(nf&1)*2+1]);
        }

        if (++kc == nk) {
            kc = 0;
            int r0 = (int)bmrow + wm*32;
            #pragma unroll
            for (int mf = 0; mf < 2; mf++) {
                #pragma unroll
                for (int nf = 0; nf < 8; nf++) {
                    int lc = wn*64 + nf*8 + (lane & 3)*2;
                    int col = bn*BN + lc;
                    int row = r0 + mf*16 + (lane >> 2);
                    float bx = sbias[lc], by = sbias[lc + 1];
                    float v0 = acc[mf][nf][0] + bx;
                    float v1 = acc[mf][nf][1] + by;
                    float v2 = acc[mf][nf][2] + bx;
                    float v3 = acc[mf][nf][3] + by;
                    size_t off0 = (size_t)row * N + col;
                    size_t off1 = (size_t)(row + 8) * N + col;
                    if (EPI == 1) {
                        v0 = gelu_exact(v0); v1 = gelu_exact(v1);
                        v2 = gelu_exact(v2); v3 = gelu_exact(v3);
                    }
                    if (EPI == 2) {
                        float2 rr0 = *(const float2*)(Res + off0);
                        float2 rr1 = *(const float2*)(Res + off1);
                        v0 += rr0.x; v1 += rr0.y;
                        v2 += rr1.x; v3 += rr1.y;
                        *(float2*)(C + off0) = make_float2(v0, v1);
                        *(float2*)(C + off1) = make_float2(v2, v3);
                    } else {
                        *(__half2*)(Ch + off0) = __floats2half2_rn(v0, v1);
                        *(__half2*)(Ch + off1) = __floats2half2_rn(v2, v3);
                    }
                    acc[mf][nf][0] = 0.0f; acc[mf][nf][1] = 0.0f;
                    acc[mf][nf][2] = 0.0f; acc[mf][nf][3] = 0.0f;
                }
            }
            bmrow += rowStride;
        }
    }
}

// ---------------- Tensor-core windowed attention, bias-matrix version --------
// Q pre-scaled in staging; bias read as coalesced half2 from the precomputed
// L2-resident matrix; no-max softmax (scores bounded).
#define QSTR 40

template<bool SHIFT>
__global__ __launch_bounds__(256, 3)
void attn_kernel(const __half* __restrict__ qkv,
                 const __half* __restrict__ bmat,
                 __half* __restrict__ out)
{
    __shared__ __half sq [128*QSTR];
    __shared__ __half skk[128*QSTR];
    __shared__ __half svv[128*QSTR];
    __shared__ int   slab [128];
    __shared__ int   stok [128];

    int tid  = threadIdx.x;
    int lane = tid & 31;
    int wm   = tid >> 5;
    int head = blockIdx.y;
    int win  = blockIdx.x;

    if (tid < 128) {
        int n = tid;
        int b  = win >> 8;
        int r  = win & 255;
        int wt = r >> 6, wh = (r >> 3) & 7, wwi = r & 7;
        int ti = n >> 6, hi = (n >> 3) & 7, wi  = n & 7;
        int pt = wt*2 + ti, ph = wh*8 + hi, pw = wwi*8 + wi;
        int t, h, w;
        if (SHIFT) { t = (pt + 1) & 7; h = (ph + 4) & 63; w = (pw + 4) & 63; }
        else       { t = pt;           h = ph;            w = pw; }
        int tok = ((b*TT + t)*HH + h)*WW + w;
        stok[n]  = tok;
        if (SHIFT) {
            int lt = pt < 6  ? 0 : (pt < 7  ? 1 : 2);
            int lh = ph < 56 ? 0 : (ph < 60 ? 1 : 2);
            int lw = pw < 56 ? 0 : (pw < 60 ? 1 : 2);
            slab[n] = lt*9 + lh*3 + lw;
        }
        const uint4* qp = (const uint4*)(qkv + (size_t)tok * QKV_N + head * HD);
        __half2 sc2 = __float2half2_rn(SCALE);
        #pragma unroll
        for (int i = 0; i < 4; i++) {
            uint4 q4 = qp[i];
            __half2* qh = (__half2*)&q4;
            qh[0] = __hmul2(qh[0], sc2); qh[1] = __hmul2(qh[1], sc2);
            qh[2] = __hmul2(qh[2], sc2); qh[3] = __hmul2(qh[3], sc2);
            *(uint4*)(sq  + n*QSTR + 8*i) = q4;
            *(uint4*)(skk + n*QSTR + 8*i) = qp[32 + i];
            *(uint4*)(svv + n*QSTR + 8*i) = qp[64 + i];
        }
    }
    __syncthreads();

    float sc[16][4];
    #pragma unroll
    for (int nt = 0; nt < 16; nt++)
        #pragma unroll
        for (int v = 0; v < 4; v++) sc[nt][v] = 0.0f;

    int lrow = lane & 15;
    int lcol = (lane >> 4) * 8;
    #pragma unroll
    for (int ks = 0; ks < 2; ks++) {
        uint32_t qa[4];
        ldsm_x4(qa, sq + (wm*16 + lrow)*QSTR + ks*16 + lcol);
        #pragma unroll
        for (int ntp = 0; ntp < 8; ntp++) {
            uint32_t kb[4];
            ldsm_x4(kb, skk + (ntp*16 + lrow)*QSTR + ks*16 + lcol);
            mma_f16(sc[ntp*2],     qa, kb[0], kb[2]);
            mma_f16(sc[ntp*2 + 1], qa, kb[1], kb[3]);
        }
    }

    // bias (precomputed matrix) + mask + exp (no max) + row-sum
    const __half2* bm2 = (const __half2*)(bmat + (size_t)head * 128 * 128);
    int irow[2], ilab[2];
    #pragma unroll
    for (int hh = 0; hh < 2; hh++) {
        irow[hh] = wm*16 + (lane >> 2) + hh*8;
        if (SHIFT) ilab[hh] = slab[irow[hh]];
    }

    float sum_[2] = {0.0f, 0.0f};
    #pragma unroll
    for (int nt = 0; nt < 16; nt++) {
        int j0 = nt*8 + (lane & 3)*2;
        int lb0 = 0, lb1 = 0;
        if (SHIFT) { lb0 = slab[j0]; lb1 = slab[j0 + 1]; }
        #pragma unroll
        for (int hh = 0; hh < 2; hh++) {
            float2 bf = __half22float2(__ldg(bm2 + ((irow[hh] << 7) + j0 >> 1)));
            float v0 = sc[nt][hh*2]   + bf.x;
            float v1 = sc[nt][hh*2+1] + bf.y;
            if (SHIFT) {
                if (lb0 != ilab[hh]) v0 -= 100.0f;
                if (lb1 != ilab[hh]) v1 -= 100.0f;
            }
            float e0 = __expf(v0);
            float e1 = __expf(v1);
            sc[nt][hh*2]   = e0;
            sc[nt][hh*2+1] = e1;
            sum_[hh] += e0 + e1;
        }
    }
    float inv_[2];
    #pragma unroll
    for (int hh = 0; hh < 2; hh++) {
        float s = sum_[hh];
        s += __shfl_xor_sync(0xffffffffu, s, 1);
        s += __shfl_xor_sync(0xffffffffu, s, 2);
        inv_[hh] = 1.0f / s;
    }

    float oc[4][4];
    #pragma unroll
    for (int nt = 0; nt < 4; nt++)
        #pragma unroll
        for (int v = 0; v < 4; v++) oc[nt][v] = 0.0f;

    #pragma unroll
    for (int s = 0; s < 8; s++) {
        uint32_t pa[4];
        pa[0] = packh2(sc[2*s][0],   sc[2*s][1]);
        pa[1] = packh2(sc[2*s][2],   sc[2*s][3]);
        pa[2] = packh2(sc[2*s+1][0], sc[2*s+1][1]);
        pa[3] = packh2(sc[2*s+1][2], sc[2*s+1][3]);
        #pragma unroll
        for (int gg = 0; gg < 2; gg++) {
            uint32_t vb[4];
            ldsm_x4t(vb, svv + (s*16 + lrow)*QSTR + lcol + gg*16);
            mma_f16(oc[gg*2],     pa, vb[0], vb[1]);
            mma_f16(oc[gg*2 + 1], pa, vb[2], vb[3]);
        }
    }

    int i0 = wm*16 + (lane >> 2);
    int tok0 = stok[i0], tok1 = stok[i0 + 8];
    float in0 = inv_[0], in1 = inv_[1];
    #pragma unroll
    for (int nt = 0; nt < 4; nt++) {
        int col = head*HD + nt*8 + (lane & 3)*2;
        *(__half2*)(out + (size_t)tok0*CC + col) =
            __floats2half2_rn(oc[nt][0]*in0, oc[nt][1]*in0);
        *(__half2*)(out + (size_t)tok1*CC + col) =
            __floats2half2_rn(oc[nt][2]*in1, oc[nt][3]*in1);
    }
}

// ---------------- host orchestration ----------------
extern "C" void kernel_launch(void* const* d_in, const int* in_sizes, int n_in,
                              void* d_out, int out_size)
{
    const float* x       = (const float*)d_in[0];
    const float* rpb1    = (const float*)d_in[1];
    const float* qkv_w1  = (const float*)d_in[2];
    const float* qkv_b1  = (const float*)d_in[3];
    const float* proj_w1 = (const float*)d_in[4];
    const float* proj_b1 = (const float*)d_in[5];
    const float* rpb2    = (const float*)d_in[6];
    const float* qkv_w2  = (const float*)d_in[7];
    const float* qkv_b2  = (const float*)d_in[8];
    const float* proj_w2 = (const float*)d_in[9];
    const float* proj_b2 = (const float*)d_in[10];
    const float* g1  = (const float*)d_in[11];
    const float* be1 = (const float*)d_in[12];
    const float* g2  = (const float*)d_in[13];
    const float* be2 = (const float*)d_in[14];
    const float* g3  = (const float*)d_in[15];
    const float* be3 = (const float*)d_in[16];
    const float* g4  = (const float*)d_in[17];
    const float* be4 = (const float*)d_in[18];
    const float* m1w1 = (const float*)d_in[19];
    const float* m1b1 = (const float*)d_in[20];
    const float* m1w2 = (const float*)d_in[21];
    const float* m1b2 = (const float*)d_in[22];
    const float* m2w1 = (const float*)d_in[23];
    const float* m2b1 = (const float*)d_in[24];
    const float* m2w2 = (const float*)d_in[25];
    const float* m2b2 = (const float*)d_in[26];
    float* out = (float*)d_out;

    __half *xnh, *qkvh, *atth, *hidh, *wh, *bm;
    float *xb;
    cudaGetSymbolAddress((void**)&xnh,  g_xnh);
    cudaGetSymbolAddress((void**)&qkvh, g_qkvh);
    cudaGetSymbolAddress((void**)&atth, g_atth);
    cudaGetSymbolAddress((void**)&hidh, g_hidh);
    cudaGetSymbolAddress((void**)&xb,   g_x);
    cudaGetSymbolAddress((void**)&wh,   g_wh);
    cudaGetSymbolAddress((void**)&bm,   g_bm);

    cudaFuncSetAttribute(hgemm_kernel<0>,
        cudaFuncAttributeMaxDynamicSharedMemorySize, GSMEM_BYTES);
    cudaFuncSetAttribute(hgemm_kernel<1>,
        cudaFuncAttributeMaxDynamicSharedMemorySize, GSMEM_BYTES);
    cudaFuncSetAttribute(hgemm_kernel<2>,
        cudaFuncAttributeMaxDynamicSharedMemorySize, GSMEM_BYTES);

    // fused weight convert + bias-matrix precompute
    {
        CvtArgs a;
        const float* srcs[8] = {qkv_w1, proj_w1, m1w1, m1w2,
                                qkv_w2, proj_w2, m2w1, m2w2};
        const int offs[8] = {OFF_QKV1, OFF_PROJ1, OFF_M1W1, OFF_M1W2,
                             OFF_QKV2, OFF_PROJ2, OFF_M2W1, OFF_M2W2};
        const int ns[8] = {CC*QKV_N, CC*CC, CC*HID, HID*CC,
                           CC*QKV_N, CC*CC, CC*HID, HID*CC};
        int cum = 0;
        for (int i = 0; i < 8; i++) {
            a.src[i] = srcs[i];
            a.dstoff[i] = offs[i];
            a.cum[i] = cum;
            cum += ns[i] / 4;
        }
        a.cum[8] = cum;
        cvt8_kernel<<<(cum + 255)/256, 256>>>(a, wh);
        biasmat_kernel<<<NHEAD, 256>>>(rpb1, bm);
        biasmat_kernel<<<NHEAD, 256>>>(rpb2, bm + NHEAD*128*128);
    }

    const int M = NTOK;
    dim3 lnGrid(M / 8);
    dim3 attnGrid(NWIN, NHEAD);

    dim3 gQKV (QKV_N/128, 49);
    dim3 gPROJ(CC/128,    148);
    dim3 gMLP1(HID/128,   74);
    dim3 gMLP2(CC/128,    148);

    // ---- block 1 ----
    ln_kernel<<<lnGrid, 256>>>(x, g1, be1, xnh);
    hgemm_kernel<0><<<gQKV, 256, GSMEM_BYTES>>>(M, QKV_N, CC, xnh, wh+OFF_QKV1, qkv_b1, nullptr, nullptr, qkvh);
    attn_kernel<false><<<attnGrid, 256>>>(qkvh, bm, atth);
    hgemm_kernel<2><<<gPROJ, 256, GSMEM_BYTES>>>(M, CC, CC, atth, wh+OFF_PROJ1, proj_b1, x, xb, nullptr);
    ln_kernel<<<lnGrid, 256>>>(xb, g2, be2, xnh);
    hgemm_kernel<1><<<gMLP1, 256, GSMEM_BYTES>>>(M, HID, CC, xnh, wh+OFF_M1W1, m1b1, nullptr, nullptr, hidh);
    hgemm_kernel<2><<<gMLP2, 256, GSMEM_BYTES>>>(M, CC, HID, hidh, wh+OFF_M1W2, m1b2, xb, xb, nullptr);

    // ---- block 2 (shifted) ----
    ln_kernel<<<lnGrid, 256>>>(xb, g3, be3, xnh);
    hgemm_kernel<0><<<gQKV, 256, GSMEM_BYTES>>>(M, QKV_N, CC, xnh, wh+OFF_QKV2, qkv_b2, nullptr, nullptr, qkvh);
    attn_kernel<true><<<attnGrid, 256>>>(qkvh, bm + NHEAD*128*128, atth);
    hgemm_kernel<2><<<gPROJ, 256, GSMEM_BYTES>>>(M, CC, CC, atth, wh+OFF_PROJ2, proj_b2, xb, xb, nullptr);
    ln_kernel<<<lnGrid, 256>>>(xb, g4, be4, xnh);
    hgemm_kernel<1><<<gMLP1, 256, GSMEM_BYTES>>>(M, HID, CC, xnh, wh+OFF_M2W1, m2b1, nullptr, nullptr, hidh);
    hgemm_kernel<2><<<gMLP2, 256, GSMEM_BYTES>>>(M, CC, HID, hidh, wh+OFF_M2W2, m2b2, xb, out, nullptr);
}

// round 15
// speedup vs baseline: 1.0711x; 1.0711x over previous
#include <cuda_runtime.h>
#include <cuda_bf16.h>
#include <cuda_fp16.h>
#include <cstdint>

// Problem constants
#define BATCH 4
#define TT 8
#define HH 64
#define WW 64
#define CC 256
#define NTOK (BATCH*TT*HH*WW)          // 131072 tokens
#define NHEAD 8
#define HD 32
#define NWIN 1024
#define QKV_N 768
#define HID 512
#define SCALE 0.17677669529663687f     // 1/sqrt(32)

// ---------------- scratch ----------------
__device__ __half g_xnh [NTOK * CC];
__device__ __half g_qkvh[NTOK * QKV_N];
__device__ __half g_atth[NTOK * CC];
__device__ __half g_hidh[NTOK * HID];
__device__ float  g_x   [NTOK * CC];
__device__ __half g_wh  [1048576];

#define OFF_QKV1 0
#define OFF_PROJ1 196608
#define OFF_M1W1 262144
#define OFF_M1W2 393216
#define OFF_QKV2 524288
#define OFF_PROJ2 720896
#define OFF_M2W1 786432
#define OFF_M2W2 917504

// ---------------- fused f32 -> f16 convert for all 8 weight matrices ----------
struct CvtArgs {
    const float* src[8];
    int dstoff[8];
    int cum[9];
};
__global__ __launch_bounds__(256)
void cvt8_kernel(CvtArgs a, __half* __restrict__ dst)
{
    int gid = blockIdx.x * 256 + threadIdx.x;
    int seg = 0;
    #pragma unroll
    for (int s = 1; s < 8; s++) seg += (gid >= a.cum[s]);
    int local = gid - a.cum[seg];
    if (gid >= a.cum[8]) return;
    const float4 v = *((const float4*)a.src[seg] + local);
    __half2 p0 = __floats2half2_rn(v.x, v.y);
    __half2 p1 = __floats2half2_rn(v.z, v.w);
    *(uint2*)(dst + a.dstoff[seg] + local*4) =
        make_uint2(*(uint32_t*)&p0, *(uint32_t*)&p1);
}

// ---------------- LayerNorm: one warp per token, fp16 out ----------------
__global__ __launch_bounds__(256)
void ln_kernel(const float* __restrict__ x, const float* __restrict__ g,
               const float* __restrict__ b, __half* __restrict__ out)
{
    int gw   = (blockIdx.x * blockDim.x + threadIdx.x) >> 5;
    int lane = threadIdx.x & 31;
    if (gw >= NTOK) return;
    const float4* row = (const float4*)(x + (size_t)gw * CC);
    float4 v0 = row[2*lane];
    float4 v1 = row[2*lane + 1];
    float s = v0.x+v0.y+v0.z+v0.w + v1.x+v1.y+v1.z+v1.w;
    float q = v0.x*v0.x+v0.y*v0.y+v0.z*v0.z+v0.w*v0.w
            + v1.x*v1.x+v1.y*v1.y+v1.z*v1.z+v1.w*v1.w;
    #pragma unroll
    for (int o = 16; o > 0; o >>= 1) {
        s += __shfl_xor_sync(0xffffffffu, s, o);
        q += __shfl_xor_sync(0xffffffffu, q, o);
    }
    float mean = s * (1.0f/256.0f);
    float var  = q * (1.0f/256.0f) - mean*mean;
    float rstd = rsqrtf(var + 1e-5f);
    const float4* g4 = (const float4*)g;
    const float4* b4 = (const float4*)b;
    float4 ga = g4[2*lane], gb2 = g4[2*lane + 1];
    float4 ba = b4[2*lane], bb2 = b4[2*lane + 1];
    __half2 h0 = __floats2half2_rn((v0.x-mean)*rstd*ga.x  + ba.x,
                                   (v0.y-mean)*rstd*ga.y  + ba.y);
    __half2 h1 = __floats2half2_rn((v0.z-mean)*rstd*ga.z  + ba.z,
                                   (v0.w-mean)*rstd*ga.w  + ba.w);
    __half2 h2 = __floats2half2_rn((v1.x-mean)*rstd*gb2.x + bb2.x,
                                   (v1.y-mean)*rstd*gb2.y + bb2.y);
    __half2 h3 = __floats2half2_rn((v1.z-mean)*rstd*gb2.z + bb2.z,
                                   (v1.w-mean)*rstd*gb2.w + bb2.w);
    uint4 pack = make_uint4(*(uint32_t*)&h0, *(uint32_t*)&h1,
                            *(uint32_t*)&h2, *(uint32_t*)&h3);
    ((uint4*)(out + (size_t)gw * CC))[lane] = pack;
}

// ---------------- shared MMA helpers ----------------
__device__ __forceinline__ void ldsm_x4(uint32_t* r, const __half* p) {
    uint32_t a = (uint32_t)__cvta_generic_to_shared(p);
    asm volatile("ldmatrix.sync.aligned.m8n8.x4.shared.b16 {%0,%1,%2,%3}, [%4];"
        : "=r"(r[0]), "=r"(r[1]), "=r"(r[2]), "=r"(r[3]) : "r"(a));
}
__device__ __forceinline__ void ldsm_x4t(uint32_t* r, const __half* p) {
    uint32_t a = (uint32_t)__cvta_generic_to_shared(p);
    asm volatile("ldmatrix.sync.aligned.m8n8.x4.trans.shared.b16 {%0,%1,%2,%3}, [%4];"
        : "=r"(r[0]), "=r"(r[1]), "=r"(r[2]), "=r"(r[3]) : "r"(a));
}
__device__ __forceinline__ void mma_f16(float* c, const uint32_t* a,
                                        uint32_t b0, uint32_t b1) {
    asm volatile(
        "mma.sync.aligned.m16n8k16.row.col.f32.f16.f16.f32 "
        "{%0,%1,%2,%3}, {%4,%5,%6,%7}, {%8,%9}, {%0,%1,%2,%3};"
        : "+f"(c[0]), "+f"(c[1]), "+f"(c[2]), "+f"(c[3])
        : "r"(a[0]), "r"(a[1]), "r"(a[2]), "r"(a[3]), "r"(b0), "r"(b1));
}
__device__ __forceinline__ uint32_t packh2(float x0, float x1) {
    __half2 p = __floats2half2_rn(x0, x1);
    return *(uint32_t*)&p;
}
__device__ __forceinline__ float gelu_exact(float x) {
    return 0.5f * x * (1.0f + erff(x * 0.7071067811865475f));
}
__device__ __forceinline__ void cpa16(const __half* g, __half* s) {
    uint32_t sa = (uint32_t)__cvta_generic_to_shared(s);
    asm volatile("cp.async.cg.shared.global [%0], [%1], 16;" :: "r"(sa), "l"(g));
}

// ---------------- persistent fp16 tensor-core GEMM (R11 config, frozen) -------
#define BM 128
#define BN 128
#define BK 32
#define NSTAGE 4
#define ASTR 40
#define BSTR 136
#define STAGE_H (BM*ASTR + BK*BSTR)
#define GSMEM_BYTES (NSTAGE * STAGE_H * 2)

template<int EPI>
__global__ __launch_bounds__(256, 2)
void hgemm_kernel(int M, int N, int K,
                  const __half* __restrict__ A,
                  const __half* __restrict__ B,
                  const float* __restrict__ bias,
                  const float* __restrict__ Res,
                  float* __restrict__ C,
                  __half* __restrict__ Ch)
{
    extern __shared__ __half smg[];
    __shared__ float sbias[128];

    int tid  = threadIdx.x;
    int bn   = blockIdx.x;
    int warp = tid >> 5, lane = tid & 31;
    int wm   = warp >> 1, wn = warp & 1;

    const __half* Bb = B + bn * BN;
    if (tid < 128) sbias[tid] = __ldg(bias + bn*BN + tid);

    int ar = tid >> 2, ac = (tid & 3) * 8;
    int br = tid >> 4, bc = (tid & 15) * 8;

    int MT = M >> 7;
    int ntiles = (MT - blockIdx.y + gridDim.y - 1) / gridDim.y;
    int nk = K / BK;
    int total = ntiles * nk;
    size_t rowStride = (size_t)gridDim.y * 128;

    float acc[2][8][4];
    #pragma unroll
    for (int i = 0; i < 2; i++)
        #pragma unroll
        for (int j = 0; j < 8; j++)
            #pragma unroll
            for (int k = 0; k < 4; k++) acc[i][j][k] = 0.0f;

    const __half* Aload = A + (size_t)blockIdx.y * 128 * K;
    int k_load = 0;

    #pragma unroll
    for (int s = 0; s < NSTAGE-1; s++) {
        __half* As = smg + s * STAGE_H;
        __half* Bs = As + BM*ASTR;
        int kcol = k_load * BK;
        cpa16(Aload + (size_t)ar * K + kcol + ac,        As + ar*ASTR + ac);
        cpa16(Aload + (size_t)(ar+64) * K + kcol + ac,   As + (ar+64)*ASTR + ac);
        cpa16(Bb + (size_t)(kcol + br) * N + bc,         Bs + br*BSTR + bc);
        cpa16(Bb + (size_t)(kcol + br + 16) * N + bc,    Bs + (br+16)*BSTR + bc);
        asm volatile("cp.async.commit_group;");
        k_load++;
    }

    int arow = wm*32 + (lane & 15);
    int aoff = (lane >> 4) * 8;
    int brow = lane & 15;
    int bcol = wn*64 + (lane >> 4) * 8;

    int kc = 0;
    size_t bmrow = (size_t)blockIdx.y * 128;

    for (int c = 0; c < total; c++) {
        asm volatile("cp.async.wait_group %0;" :: "n"(NSTAGE-2));
        __syncthreads();

        if (c + NSTAGE-1 < total) {
            __half* As = smg + ((c + NSTAGE-1) & (NSTAGE-1)) * STAGE_H;
            __half* Bs = As + BM*ASTR;
            int kcol = k_load * BK;
            cpa16(Aload + (size_t)ar * K + kcol + ac,        As + ar*ASTR + ac);
            cpa16(Aload + (size_t)(ar+64) * K + kcol + ac,   As + (ar+64)*ASTR + ac);
            cpa16(Bb + (size_t)(kcol + br) * N + bc,         Bs + br*BSTR + bc);
            cpa16(Bb + (size_t)(kcol + br + 16) * N + bc,    Bs + (br+16)*BSTR + bc);
            if (++k_load == nk) { k_load = 0; Aload += rowStride * K; }
        }
        asm volatile("cp.async.commit_group;");

        const __half* As = smg + (c & (NSTAGE-1)) * STAGE_H;
        const __half* Bs = As + BM*ASTR;

        #pragma unroll
        for (int kk = 0; kk < BK; kk += 16) {
            uint32_t af[2][4], bf[4][4];
            #pragma unroll
            for (int mf = 0; mf < 2; mf++)
                ldsm_x4(af[mf], As + (arow + mf*16)*ASTR + kk + aoff);
            #pragma unroll
            for (int gg = 0; gg < 4; gg++)
                ldsm_x4t(bf[gg], Bs + (kk + brow)*BSTR + bcol + gg*16);
            #pragma unroll
            for (int mf = 0; mf < 2; mf++)
                #pragma unroll
                for (int nf = 0; nf < 8; nf++)
                    mma_f16(acc[mf][nf], af[mf],
                            bf[nf>>1][(nf&1)*2], bf[nf>>1][(nf&1)*2+1]);
        }

        if (++kc == nk) {
            kc = 0;
            int r0 = (int)bmrow + wm*32;
            #pragma unroll
            for (int mf = 0; mf < 2; mf++) {
                #pragma unroll
                for (int nf = 0; nf < 8; nf++) {
                    int lc = wn*64 + nf*8 + (lane & 3)*2;
                    int col = bn*BN + lc;
                    int row = r0 + mf*16 + (lane >> 2);
                    float bx = sbias[lc], by = sbias[lc + 1];
                    float v0 = acc[mf][nf][0] + bx;
                    float v1 = acc[mf][nf][1] + by;
                    float v2 = acc[mf][nf][2] + bx;
                    float v3 = acc[mf][nf][3] + by;
                    size_t off0 = (size_t)row * N + col;
                    size_t off1 = (size_t)(row + 8) * N + col;
                    if (EPI == 1) {
                        v0 = gelu_exact(v0); v1 = gelu_exact(v1);
                        v2 = gelu_exact(v2); v3 = gelu_exact(v3);
                    }
                    if (EPI == 2) {
                        float2 rr0 = *(const float2*)(Res + off0);
                        float2 rr1 = *(const float2*)(Res + off1);
                        v0 += rr0.x; v1 += rr0.y;
                        v2 += rr1.x; v3 += rr1.y;
                        *(float2*)(C + off0) = make_float2(v0, v1);
                        *(float2*)(C + off1) = make_float2(v2, v3);
                    } else {
                        *(__half2*)(Ch + off0) = __floats2half2_rn(v0, v1);
                        *(__half2*)(Ch + off1) = __floats2half2_rn(v2, v3);
                    }
                    acc[mf][nf][0] = 0.0f; acc[mf][nf][1] = 0.0f;
                    acc[mf][nf][2] = 0.0f; acc[mf][nf][3] = 0.0f;
                }
            }
            bmrow += rowStride;
        }
    }
}

// ---------------- Tensor-core windowed attention (R13 + balanced staging) -----
// smem rbias + on-the-fly rel index (proven fastest); no-max softmax; staging
// split across all 256 threads (2 threads per token).
#define QSTR 40

template<bool SHIFT>
__global__ __launch_bounds__(256, 3)
void attn_kernel(const __half* __restrict__ qkv,
                 const float* __restrict__ rpb,
                 __half* __restrict__ out)
{
    __shared__ __half sq [128*QSTR];
    __shared__ __half skk[128*QSTR];
    __shared__ __half svv[128*QSTR];
    __shared__ float rbias[675];
    __shared__ int   sbase[128];
    __shared__ int   slab [128];
    __shared__ int   stok [128];

    int tid  = threadIdx.x;
    int lane = tid & 31;
    int wm   = tid >> 5;
    int head = blockIdx.y;
    int win  = blockIdx.x;

    // staging: 2 threads per token, each stages 2 of the 4 uint4 per tensor
    {
        int n    = tid >> 1;
        int half = tid & 1;
        int b  = win >> 8;
        int r  = win & 255;
        int wt = r >> 6, wh = (r >> 3) & 7, wwi = r & 7;
        int ti = n >> 6, hi = (n >> 3) & 7, wi  = n & 7;
        int pt = wt*2 + ti, ph = wh*8 + hi, pw = wwi*8 + wi;
        int t, h, w;
        if (SHIFT) { t = (pt + 1) & 7; h = (ph + 4) & 63; w = (pw + 4) & 63; }
        else       { t = pt;           h = ph;            w = pw; }
        int tok = ((b*TT + t)*HH + h)*WW + w;
        if (half == 0) {
            stok[n]  = tok;
            sbase[n] = ti*225 + hi*15 + wi;
            if (SHIFT) {
                int lt = pt < 6  ? 0 : (pt < 7  ? 1 : 2);
                int lh = ph < 56 ? 0 : (ph < 60 ? 1 : 2);
                int lw = pw < 56 ? 0 : (pw < 60 ? 1 : 2);
                slab[n] = lt*9 + lh*3 + lw;
            }
        }
        const uint4* qp = (const uint4*)(qkv + (size_t)tok * QKV_N + head * HD);
        #pragma unroll
        for (int i = 0; i < 2; i++) {
            int idx = half*2 + i;
            *(uint4*)(sq  + n*QSTR + 8*idx) = qp[idx];
            *(uint4*)(skk + n*QSTR + 8*idx) = qp[32 + idx];
            *(uint4*)(svv + n*QSTR + 8*idx) = qp[64 + idx];
        }
    }
    for (int i = tid; i < 675; i += 256)
        rbias[i] = __ldg(rpb + i*NHEAD + head);
    __syncthreads();

    float sc[16][4];
    #pragma unroll
    for (int nt = 0; nt < 16; nt++)
        #pragma unroll
        for (int v = 0; v < 4; v++) sc[nt][v] = 0.0f;

    int lrow = lane & 15;
    int lcol = (lane >> 4) * 8;
    #pragma unroll
    for (int ks = 0; ks < 2; ks++) {
        uint32_t qa[4];
        ldsm_x4(qa, sq + (wm*16 + lrow)*QSTR + ks*16 + lcol);
        #pragma unroll
        for (int ntp = 0; ntp < 8; ntp++) {
            uint32_t kb[4];
            ldsm_x4(kb, skk + (ntp*16 + lrow)*QSTR + ks*16 + lcol);
            mma_f16(sc[ntp*2],     qa, kb[0], kb[2]);
            mma_f16(sc[ntp*2 + 1], qa, kb[1], kb[3]);
        }
    }

    int ibase[2], ilab[2];
    #pragma unroll
    for (int hh = 0; hh < 2; hh++) {
        int i = wm*16 + (lane >> 2) + hh*8;
        ibase[hh] = sbase[i] + 337;
        if (SHIFT) ilab[hh] = slab[i];
    }

    // bias + mask + exp (no max subtraction) + row-sum
    float sum_[2] = {0.0f, 0.0f};
    #pragma unroll
    for (int nt = 0; nt < 16; nt++) {
        int j0 = nt*8 + (lane & 3)*2;
        int bs0 = sbase[j0], bs1 = sbase[j0 + 1];
        int lb0 = 0, lb1 = 0;
        if (SHIFT) { lb0 = slab[j0]; lb1 = slab[j0 + 1]; }
        #pragma unroll
        for (int hh = 0; hh < 2; hh++) {
            float v0 = sc[nt][hh*2]   * SCALE + rbias[ibase[hh] - bs0];
            float v1 = sc[nt][hh*2+1] * SCALE + rbias[ibase[hh] - bs1];
            if (SHIFT) {
                if (lb0 != ilab[hh]) v0 -= 100.0f;
                if (lb1 != ilab[hh]) v1 -= 100.0f;
            }
            float e0 = __expf(v0);
            float e1 = __expf(v1);
            sc[nt][hh*2]   = e0;
            sc[nt][hh*2+1] = e1;
            sum_[hh] += e0 + e1;
        }
    }
    float inv_[2];
    #pragma unroll
    for (int hh = 0; hh < 2; hh++) {
        float s = sum_[hh];
        s += __shfl_xor_sync(0xffffffffu, s, 1);
        s += __shfl_xor_sync(0xffffffffu, s, 2);
        inv_[hh] = 1.0f / s;
    }

    float oc[4][4];
    #pragma unroll
    for (int nt = 0; nt < 4; nt++)
        #pragma unroll
        for (int v = 0; v < 4; v++) oc[nt][v] = 0.0f;

    #pragma unroll
    for (int s = 0; s < 8; s++) {
        uint32_t pa[4];
        pa[0] = packh2(sc[2*s][0],   sc[2*s][1]);
        pa[1] = packh2(sc[2*s][2],   sc[2*s][3]);
        pa[2] = packh2(sc[2*s+1][0], sc[2*s+1][1]);
        pa[3] = packh2(sc[2*s+1][2], sc[2*s+1][3]);
        #pragma unroll
        for (int gg = 0; gg < 2; gg++) {
            uint32_t vb[4];
            ldsm_x4t(vb, svv + (s*16 + lrow)*QSTR + lcol + gg*16);
            mma_f16(oc[gg*2],     pa, vb[0], vb[1]);
            mma_f16(oc[gg*2 + 1], pa, vb[2], vb[3]);
        }
    }

    int i0 = wm*16 + (lane >> 2);
    int tok0 = stok[i0], tok1 = stok[i0 + 8];
    float in0 = inv_[0], in1 = inv_[1];
    #pragma unroll
    for (int nt = 0; nt < 4; nt++) {
        int col = head*HD + nt*8 + (lane & 3)*2;
        *(__half2*)(out + (size_t)tok0*CC + col) =
            __floats2half2_rn(oc[nt][0]*in0, oc[nt][1]*in0);
        *(__half2*)(out + (size_t)tok1*CC + col) =
            __floats2half2_rn(oc[nt][2]*in1, oc[nt][3]*in1);
    }
}

// ---------------- host orchestration ----------------
extern "C" void kernel_launch(void* const* d_in, const int* in_sizes, int n_in,
                              void* d_out, int out_size)
{
    const float* x       = (const float*)d_in[0];
    const float* rpb1    = (const float*)d_in[1];
    const float* qkv_w1  = (const float*)d_in[2];
    const float* qkv_b1  = (const float*)d_in[3];
    const float* proj_w1 = (const float*)d_in[4];
    const float* proj_b1 = (const float*)d_in[5];
    const float* rpb2    = (const float*)d_in[6];
    const float* qkv_w2  = (const float*)d_in[7];
    const float* qkv_b2  = (const float*)d_in[8];
    const float* proj_w2 = (const float*)d_in[9];
    const float* proj_b2 = (const float*)d_in[10];
    const float* g1  = (const float*)d_in[11];
    const float* be1 = (const float*)d_in[12];
    const float* g2  = (const float*)d_in[13];
    const float* be2 = (const float*)d_in[14];
    const float* g3  = (const float*)d_in[15];
    const float* be3 = (const float*)d_in[16];
    const float* g4  = (const float*)d_in[17];
    const float* be4 = (const float*)d_in[18];
    const float* m1w1 = (const float*)d_in[19];
    const float* m1b1 = (const float*)d_in[20];
    const float* m1w2 = (const float*)d_in[21];
    const float* m1b2 = (const float*)d_in[22];
    const float* m2w1 = (const float*)d_in[23];
    const float* m2b1 = (const float*)d_in[24];
    const float* m2w2 = (const float*)d_in[25];
    const float* m2b2 = (const float*)d_in[26];
    float* out = (float*)d_out;

    __half *xnh, *qkvh, *atth, *hidh, *wh;
    float *xb;
    cudaGetSymbolAddress((void**)&xnh,  g_xnh);
    cudaGetSymbolAddress((void**)&qkvh, g_qkvh);
    cudaGetSymbolAddress((void**)&atth, g_atth);
    cudaGetSymbolAddress((void**)&hidh, g_hidh);
    cudaGetSymbolAddress((void**)&xb,   g_x);
    cudaGetSymbolAddress((void**)&wh,   g_wh);

    cudaFuncSetAttribute(hgemm_kernel<0>,
        cudaFuncAttributeMaxDynamicSharedMemorySize, GSMEM_BYTES);
    cudaFuncSetAttribute(hgemm_kernel<1>,
        cudaFuncAttributeMaxDynamicSharedMemorySize, GSMEM_BYTES);
    cudaFuncSetAttribute(hgemm_kernel<2>,
        cudaFuncAttributeMaxDynamicSharedMemorySize, GSMEM_BYTES);

    // fused weight convert
    {
        CvtArgs a;
        const float* srcs[8] = {qkv_w1, proj_w1, m1w1, m1w2,
                                qkv_w2, proj_w2, m2w1, m2w2};
        const int offs[8] = {OFF_QKV1, OFF_PROJ1, OFF_M1W1, OFF_M1W2,
                             OFF_QKV2, OFF_PROJ2, OFF_M2W1, OFF_M2W2};
        const int ns[8] = {CC*QKV_N, CC*CC, CC*HID, HID*CC,
                           CC*QKV_N, CC*CC, CC*HID, HID*CC};
        int cum = 0;
        for (int i = 0; i < 8; i++) {
            a.src[i] = srcs[i];
            a.dstoff[i] = offs[i];
            a.cum[i] = cum;
            cum += ns[i] / 4;
        }
        a.cum[8] = cum;
        cvt8_kernel<<<(cum + 255)/256, 256>>>(a, wh);
    }

    const int M = NTOK;
    dim3 lnGrid(M / 8);
    dim3 attnGrid(NWIN, NHEAD);

    dim3 gQKV (QKV_N/128, 49);
    dim3 gPROJ(CC/128,    148);
    dim3 gMLP1(HID/128,   74);
    dim3 gMLP2(CC/128,    148);

    // ---- block 1 ----
    ln_kernel<<<lnGrid, 256>>>(x, g1, be1, xnh);
    hgemm_kernel<0><<<gQKV, 256, GSMEM_BYTES>>>(M, QKV_N, CC, xnh, wh+OFF_QKV1, qkv_b1, nullptr, nullptr, qkvh);
    attn_kernel<false><<<attnGrid, 256>>>(qkvh, rpb1, atth);
    hgemm_kernel<2><<<gPROJ, 256, GSMEM_BYTES>>>(M, CC, CC, atth, wh+OFF_PROJ1, proj_b1, x, xb, nullptr);
    ln_kernel<<<lnGrid, 256>>>(xb, g2, be2, xnh);
    hgemm_kernel<1><<<gMLP1, 256, GSMEM_BYTES>>>(M, HID, CC, xnh, wh+OFF_M1W1, m1b1, nullptr, nullptr, hidh);
    hgemm_kernel<2><<<gMLP2, 256, GSMEM_BYTES>>>(M, CC, HID, hidh, wh+OFF_M1W2, m1b2, xb, xb, nullptr);

    // ---- block 2 (shifted) ----
    ln_kernel<<<lnGrid, 256>>>(xb, g3, be3, xnh);
    hgemm_kernel<0><<<gQKV, 256, GSMEM_BYTES>>>(M, QKV_N, CC, xnh, wh+OFF_QKV2, qkv_b2, nullptr, nullptr, qkvh);
    attn_kernel<true><<<attnGrid, 256>>>(qkvh, rpb2, atth);
    hgemm_kernel<2><<<gPROJ, 256, GSMEM_BYTES>>>(M, CC, CC, atth, wh+OFF_PROJ2, proj_b2, xb, xb, nullptr);
    ln_kernel<<<lnGrid, 256>>>(xb, g4, be4, xnh);
    hgemm_kernel<1><<<gMLP1, 256, GSMEM_BYTES>>>(M, HID, CC, xnh, wh+OFF_M2W1, m2b1, nullptr, nullptr, hidh);
    hgemm_kernel<2><<<gMLP2, 256, GSMEM_BYTES>>>(M, CC, HID, hidh, wh+OFF_M2W2, m2b2, xb, out, nullptr);
}

// round 16
// speedup vs baseline: 1.0888x; 1.0165x over previous
#include <cuda_runtime.h>
#include <cuda_bf16.h>
#include <cuda_fp16.h>
#include <cstdint>

// Problem constants
#define BATCH 4
#define TT 8
#define HH 64
#define WW 64
#define CC 256
#define NTOK (BATCH*TT*HH*WW)          // 131072 tokens
#define NHEAD 8
#define HD 32
#define NWIN 1024
#define QKV_N 768
#define HID 512
#define SCALE 0.17677669529663687f     // 1/sqrt(32)

// ---------------- scratch ----------------
__device__ __half g_xnh [NTOK * CC];
__device__ __half g_qkvh[NTOK * QKV_N];
__device__ __half g_atth[NTOK * CC];
__device__ __half g_hidh[NTOK * HID];
__device__ float  g_x   [NTOK * CC];
__device__ __half g_wh  [1048576];

#define OFF_QKV1 0
#define OFF_PROJ1 196608
#define OFF_M1W1 262144
#define OFF_M1W2 393216
#define OFF_QKV2 524288
#define OFF_PROJ2 720896
#define OFF_M2W1 786432
#define OFF_M2W2 917504

// ---------------- fused f32 -> f16 convert for all 8 weight matrices ----------
struct CvtArgs {
    const float* src[8];
    int dstoff[8];
    int cum[9];
};
__global__ __launch_bounds__(256)
void cvt8_kernel(CvtArgs a, __half* __restrict__ dst)
{
    int gid = blockIdx.x * 256 + threadIdx.x;
    int seg = 0;
    #pragma unroll
    for (int s = 1; s < 8; s++) seg += (gid >= a.cum[s]);
    int local = gid - a.cum[seg];
    if (gid >= a.cum[8]) return;
    const float4 v = *((const float4*)a.src[seg] + local);
    __half2 p0 = __floats2half2_rn(v.x, v.y);
    __half2 p1 = __floats2half2_rn(v.z, v.w);
    *(uint2*)(dst + a.dstoff[seg] + local*4) =
        make_uint2(*(uint32_t*)&p0, *(uint32_t*)&p1);
}

// ---------------- LayerNorm: one warp per token, fp16 out ----------------
__global__ __launch_bounds__(256)
void ln_kernel(const float* __restrict__ x, const float* __restrict__ g,
               const float* __restrict__ b, __half* __restrict__ out)
{
    int gw   = (blockIdx.x * blockDim.x + threadIdx.x) >> 5;
    int lane = threadIdx.x & 31;
    if (gw >= NTOK) return;
    const float4* row = (const float4*)(x + (size_t)gw * CC);
    float4 v0 = row[2*lane];
    float4 v1 = row[2*lane + 1];
    float s = v0.x+v0.y+v0.z+v0.w + v1.x+v1.y+v1.z+v1.w;
    float q = v0.x*v0.x+v0.y*v0.y+v0.z*v0.z+v0.w*v0.w
            + v1.x*v1.x+v1.y*v1.y+v1.z*v1.z+v1.w*v1.w;
    #pragma unroll
    for (int o = 16; o > 0; o >>= 1) {
        s += __shfl_xor_sync(0xffffffffu, s, o);
        q += __shfl_xor_sync(0xffffffffu, q, o);
    }
    float mean = s * (1.0f/256.0f);
    float var  = q * (1.0f/256.0f) - mean*mean;
    float rstd = rsqrtf(var + 1e-5f);
    const float4* g4 = (const float4*)g;
    const float4* b4 = (const float4*)b;
    float4 ga = g4[2*lane], gb2 = g4[2*lane + 1];
    float4 ba = b4[2*lane], bb2 = b4[2*lane + 1];
    __half2 h0 = __floats2half2_rn((v0.x-mean)*rstd*ga.x  + ba.x,
                                   (v0.y-mean)*rstd*ga.y  + ba.y);
    __half2 h1 = __floats2half2_rn((v0.z-mean)*rstd*ga.z  + ba.z,
                                   (v0.w-mean)*rstd*ga.w  + ba.w);
    __half2 h2 = __floats2half2_rn((v1.x-mean)*rstd*gb2.x + bb2.x,
                                   (v1.y-mean)*rstd*gb2.y + bb2.y);
    __half2 h3 = __floats2half2_rn((v1.z-mean)*rstd*gb2.z + bb2.z,
                                   (v1.w-mean)*rstd*gb2.w + bb2.w);
    uint4 pack = make_uint4(*(uint32_t*)&h0, *(uint32_t*)&h1,
                            *(uint32_t*)&h2, *(uint32_t*)&h3);
    ((uint4*)(out + (size_t)gw * CC))[lane] = pack;
}

// ---------------- shared MMA helpers ----------------
__device__ __forceinline__ void ldsm_x4(uint32_t* r, const __half* p) {
    uint32_t a = (uint32_t)__cvta_generic_to_shared(p);
    asm volatile("ldmatrix.sync.aligned.m8n8.x4.shared.b16 {%0,%1,%2,%3}, [%4];"
        : "=r"(r[0]), "=r"(r[1]), "=r"(r[2]), "=r"(r[3]) : "r"(a));
}
__device__ __forceinline__ void ldsm_x4t(uint32_t* r, const __half* p) {
    uint32_t a = (uint32_t)__cvta_generic_to_shared(p);
    asm volatile("ldmatrix.sync.aligned.m8n8.x4.trans.shared.b16 {%0,%1,%2,%3}, [%4];"
        : "=r"(r[0]), "=r"(r[1]), "=r"(r[2]), "=r"(r[3]) : "r"(a));
}
__device__ __forceinline__ void mma_f16(float* c, const uint32_t* a,
                                        uint32_t b0, uint32_t b1) {
    asm volatile(
        "mma.sync.aligned.m16n8k16.row.col.f32.f16.f16.f32 "
        "{%0,%1,%2,%3}, {%4,%5,%6,%7}, {%8,%9}, {%0,%1,%2,%3};"
        : "+f"(c[0]), "+f"(c[1]), "+f"(c[2]), "+f"(c[3])
        : "r"(a[0]), "r"(a[1]), "r"(a[2]), "r"(a[3]), "r"(b0), "r"(b1));
}
__device__ __forceinline__ uint32_t packh2(float x0, float x1) {
    __half2 p = __floats2half2_rn(x0, x1);
    return *(uint32_t*)&p;
}
__device__ __forceinline__ float gelu_exact(float x) {
    return 0.5f * x * (1.0f + erff(x * 0.7071067811865475f));
}
__device__ __forceinline__ void cpa16(const __half* g, __half* s) {
    uint32_t sa = (uint32_t)__cvta_generic_to_shared(s);
    asm volatile("cp.async.cg.shared.global [%0], [%1], 16;" :: "r"(sa), "l"(g));
}

// ---------------- persistent fp16 GEMM: 4 warps, 64x64 warp tiles ------------
// 128x128 CTA tile, BK=32, 4 stages. mma/ldsm = 4.0 (was 2.67): L1-bound fix.
#define BM 128
#define BN 128
#define BK 32
#define NSTAGE 4
#define ASTR 40
#define BSTR 136
#define STAGE_H (BM*ASTR + BK*BSTR)
#define GSMEM_BYTES (NSTAGE * STAGE_H * 2)

template<int EPI>
__global__ __launch_bounds__(128, 2)
void hgemm_kernel(int M, int N, int K,
                  const __half* __restrict__ A,
                  const __half* __restrict__ B,
                  const float* __restrict__ bias,
                  const float* __restrict__ Res,
                  float* __restrict__ C,
                  __half* __restrict__ Ch)
{
    extern __shared__ __half smg[];
    __shared__ float sbias[128];

    int tid  = threadIdx.x;
    int bn   = blockIdx.x;
    int warp = tid >> 5, lane = tid & 31;
    int wm   = warp >> 1, wn = warp & 1;    // 2x2 warps, warp tile 64x64

    const __half* Bb = B + bn * BN;
    sbias[tid] = __ldg(bias + bn*BN + tid);

    // loader: A 128r x 32h (4 cpa16/thread), B 32r x 128h (4 cpa16/thread)
    int ar = tid >> 2, ac = (tid & 3) * 8;    // A rows ar+32g
    int br = tid >> 4, bc = (tid & 15) * 8;   // B rows br+8g

    int MT = M >> 7;
    int ntiles = (MT - blockIdx.y + gridDim.y - 1) / gridDim.y;
    int nk = K / BK;
    int total = ntiles * nk;
    size_t rowStride = (size_t)gridDim.y * 128;

    float acc[4][8][4];
    #pragma unroll
    for (int i = 0; i < 4; i++)
        #pragma unroll
        for (int j = 0; j < 8; j++)
            #pragma unroll
            for (int k = 0; k < 4; k++) acc[i][j][k] = 0.0f;

    const __half* Aload = A + (size_t)blockIdx.y * 128 * K;
    int k_load = 0;

    #pragma unroll
    for (int s = 0; s < NSTAGE-1; s++) {
        __half* As = smg + s * STAGE_H;
        __half* Bs = As + BM*ASTR;
        int kcol = k_load * BK;
        #pragma unroll
        for (int g = 0; g < 4; g++) {
            cpa16(Aload + (size_t)(ar + 32*g) * K + kcol + ac,
                  As + (ar + 32*g)*ASTR + ac);
            cpa16(Bb + (size_t)(kcol + br + 8*g) * N + bc,
                  Bs + (br + 8*g)*BSTR + bc);
        }
        asm volatile("cp.async.commit_group;");
        k_load++;
    }

    int arow = wm*64 + (lane & 15);
    int aoff = (lane >> 4) * 8;
    int brow = lane & 15;
    int bcol = wn*64 + (lane >> 4) * 8;

    int kc = 0;
    size_t bmrow = (size_t)blockIdx.y * 128;

    for (int c = 0; c < total; c++) {
        asm volatile("cp.async.wait_group %0;" :: "n"(NSTAGE-2));
        __syncthreads();

        if (c + NSTAGE-1 < total) {
            __half* As = smg + ((c + NSTAGE-1) & (NSTAGE-1)) * STAGE_H;
            __half* Bs = As + BM*ASTR;
            int kcol = k_load * BK;
            #pragma unroll
            for (int g = 0; g < 4; g++) {
                cpa16(Aload + (size_t)(ar + 32*g) * K + kcol + ac,
                      As + (ar + 32*g)*ASTR + ac);
                cpa16(Bb + (size_t)(kcol + br + 8*g) * N + bc,
                      Bs + (br + 8*g)*BSTR + bc);
            }
            if (++k_load == nk) { k_load = 0; Aload += rowStride * K; }
        }
        asm volatile("cp.async.commit_group;");

        const __half* As = smg + (c & (NSTAGE-1)) * STAGE_H;
        const __half* Bs = As + BM*ASTR;

        #pragma unroll
        for (int kk = 0; kk < BK; kk += 16) {
            uint32_t af[4][4], bf[4][4];
            #pragma unroll
            for (int mf = 0; mf < 4; mf++)
                ldsm_x4(af[mf], As + (arow + mf*16)*ASTR + kk + aoff);
            #pragma unroll
            for (int gg = 0; gg < 4; gg++)
                ldsm_x4t(bf[gg], Bs + (kk + brow)*BSTR + bcol + gg*16);
            #pragma unroll
            for (int mf = 0; mf < 4; mf++)
                #pragma unroll
                for (int nf = 0; nf < 8; nf++)
                    mma_f16(acc[mf][nf], af[mf],
                            bf[nf>>1][(nf&1)*2], bf[nf>>1][(nf&1)*2+1]);
        }

        if (++kc == nk) {
            kc = 0;
            int r0 = (int)bmrow + wm*64;
            #pragma unroll
            for (int mf = 0; mf < 4; mf++) {
                #pragma unroll
                for (int nf = 0; nf < 8; nf++) {
                    int lc = wn*64 + nf*8 + (lane & 3)*2;
                    int col = bn*BN + lc;
                    int row = r0 + mf*16 + (lane >> 2);
                    float bx = sbias[lc], by = sbias[lc + 1];
                    float v0 = acc[mf][nf][0] + bx;
                    float v1 = acc[mf][nf][1] + by;
                    float v2 = acc[mf][nf][2] + bx;
                    float v3 = acc[mf][nf][3] + by;
                    size_t off0 = (size_t)row * N + col;
                    size_t off1 = (size_t)(row + 8) * N + col;
                    if (EPI == 1) {
                        v0 = gelu_exact(v0); v1 = gelu_exact(v1);
                        v2 = gelu_exact(v2); v3 = gelu_exact(v3);
                    }
                    if (EPI == 2) {
                        float2 rr0 = *(const float2*)(Res + off0);
                        float2 rr1 = *(const float2*)(Res + off1);
                        v0 += rr0.x; v1 += rr0.y;
                        v2 += rr1.x; v3 += rr1.y;
                        *(float2*)(C + off0) = make_float2(v0, v1);
                        *(float2*)(C + off1) = make_float2(v2, v3);
                    } else {
                        *(__half2*)(Ch + off0) = __floats2half2_rn(v0, v1);
                        *(__half2*)(Ch + off1) = __floats2half2_rn(v2, v3);
                    }
                    acc[mf][nf][0] = 0.0f; acc[mf][nf][1] = 0.0f;
                    acc[mf][nf][2] = 0.0f; acc[mf][nf][3] = 0.0f;
                }
            }
            bmrow += rowStride;
        }
    }
}

// ---------------- Tensor-core windowed attention (R15 + Q prescale) ----------
#define QSTR 40

template<bool SHIFT>
__global__ __launch_bounds__(256, 3)
void attn_kernel(const __half* __restrict__ qkv,
                 const float* __restrict__ rpb,
                 __half* __restrict__ out)
{
    __shared__ __half sq [128*QSTR];
    __shared__ __half skk[128*QSTR];
    __shared__ __half svv[128*QSTR];
    __shared__ float rbias[675];
    __shared__ int   sbase[128];
    __shared__ int   slab [128];
    __shared__ int   stok [128];

    int tid  = threadIdx.x;
    int lane = tid & 31;
    int wm   = tid >> 5;
    int head = blockIdx.y;
    int win  = blockIdx.x;

    // staging: 2 threads per token; Q pre-scaled by SCALE
    {
        int n    = tid >> 1;
        int half = tid & 1;
        int b  = win >> 8;
        int r  = win & 255;
        int wt = r >> 6, wh = (r >> 3) & 7, wwi = r & 7;
        int ti = n >> 6, hi = (n >> 3) & 7, wi  = n & 7;
        int pt = wt*2 + ti, ph = wh*8 + hi, pw = wwi*8 + wi;
        int t, h, w;
        if (SHIFT) { t = (pt + 1) & 7; h = (ph + 4) & 63; w = (pw + 4) & 63; }
        else       { t = pt;           h = ph;            w = pw; }
        int tok = ((b*TT + t)*HH + h)*WW + w;
        if (half == 0) {
            stok[n]  = tok;
            sbase[n] = ti*225 + hi*15 + wi;
            if (SHIFT) {
                int lt = pt < 6  ? 0 : (pt < 7  ? 1 : 2);
                int lh = ph < 56 ? 0 : (ph < 60 ? 1 : 2);
                int lw = pw < 56 ? 0 : (pw < 60 ? 1 : 2);
                slab[n] = lt*9 + lh*3 + lw;
            }
        }
        const uint4* qp = (const uint4*)(qkv + (size_t)tok * QKV_N + head * HD);
        __half2 sc2 = __float2half2_rn(SCALE);
        #pragma unroll
        for (int i = 0; i < 2; i++) {
            int idx = half*2 + i;
            uint4 q4 = qp[idx];
            __half2* qh = (__half2*)&q4;
            qh[0] = __hmul2(qh[0], sc2); qh[1] = __hmul2(qh[1], sc2);
            qh[2] = __hmul2(qh[2], sc2); qh[3] = __hmul2(qh[3], sc2);
            *(uint4*)(sq  + n*QSTR + 8*idx) = q4;
            *(uint4*)(skk + n*QSTR + 8*idx) = qp[32 + idx];
            *(uint4*)(svv + n*QSTR + 8*idx) = qp[64 + idx];
        }
    }
    for (int i = tid; i < 675; i += 256)
        rbias[i] = __ldg(rpb + i*NHEAD + head);
    __syncthreads();

    float sc[16][4];
    #pragma unroll
    for (int nt = 0; nt < 16; nt++)
        #pragma unroll
        for (int v = 0; v < 4; v++) sc[nt][v] = 0.0f;

    int lrow = lane & 15;
    int lcol = (lane >> 4) * 8;
    #pragma unroll
    for (int ks = 0; ks < 2; ks++) {
        uint32_t qa[4];
        ldsm_x4(qa, sq + (wm*16 + lrow)*QSTR + ks*16 + lcol);
        #pragma unroll
        for (int ntp = 0; ntp < 8; ntp++) {
            uint32_t kb[4];
            ldsm_x4(kb, skk + (ntp*16 + lrow)*QSTR + ks*16 + lcol);
            mma_f16(sc[ntp*2],     qa, kb[0], kb[2]);
            mma_f16(sc[ntp*2 + 1], qa, kb[1], kb[3]);
        }
    }

    int ibase[2], ilab[2];
    #pragma unroll
    for (int hh = 0; hh < 2; hh++) {
        int i = wm*16 + (lane >> 2) + hh*8;
        ibase[hh] = sbase[i] + 337;
        if (SHIFT) ilab[hh] = slab[i];
    }

    // bias + mask + exp (no max) + row-sum (Q already scaled)
    float sum_[2] = {0.0f, 0.0f};
    #pragma unroll
    for (int nt = 0; nt < 16; nt++) {
        int j0 = nt*8 + (lane & 3)*2;
        int bs0 = sbase[j0], bs1 = sbase[j0 + 1];
        int lb0 = 0, lb1 = 0;
        if (SHIFT) { lb0 = slab[j0]; lb1 = slab[j0 + 1]; }
        #pragma unroll
        for (int hh = 0; hh < 2; hh++) {
            float v0 = sc[nt][hh*2]   + rbias[ibase[hh] - bs0];
            float v1 = sc[nt][hh*2+1] + rbias[ibase[hh] - bs1];
            if (SHIFT) {
                if (lb0 != ilab[hh]) v0 -= 100.0f;
                if (lb1 != ilab[hh]) v1 -= 100.0f;
            }
            float e0 = __expf(v0);
            float e1 = __expf(v1);
            sc[nt][hh*2]   = e0;
            sc[nt][hh*2+1] = e1;
            sum_[hh] += e0 + e1;
        }
    }
    float inv_[2];
    #pragma unroll
    for (int hh = 0; hh < 2; hh++) {
        float s = sum_[hh];
        s += __shfl_xor_sync(0xffffffffu, s, 1);
        s += __shfl_xor_sync(0xffffffffu, s, 2);
        inv_[hh] = 1.0f / s;
    }

    float oc[4][4];
    #pragma unroll
    for (int nt = 0; nt < 4; nt++)
        #pragma unroll
        for (int v = 0; v < 4; v++) oc[nt][v] = 0.0f;

    #pragma unroll
    for (int s = 0; s < 8; s++) {
        uint32_t pa[4];
        pa[0] = packh2(sc[2*s][0],   sc[2*s][1]);
        pa[1] = packh2(sc[2*s][2],   sc[2*s][3]);
        pa[2] = packh2(sc[2*s+1][0], sc[2*s+1][1]);
        pa[3] = packh2(sc[2*s+1][2], sc[2*s+1][3]);
        #pragma unroll
        for (int gg = 0; gg < 2; gg++) {
            uint32_t vb[4];
            ldsm_x4t(vb, svv + (s*16 + lrow)*QSTR + lcol + gg*16);
            mma_f16(oc[gg*2],     pa, vb[0], vb[1]);
            mma_f16(oc[gg*2 + 1], pa, vb[2], vb[3]);
        }
    }

    int i0 = wm*16 + (lane >> 2);
    int tok0 = stok[i0], tok1 = stok[i0 + 8];
    float in0 = inv_[0], in1 = inv_[1];
    #pragma unroll
    for (int nt = 0; nt < 4; nt++) {
        int col = head*HD + nt*8 + (lane & 3)*2;
        *(__half2*)(out + (size_t)tok0*CC + col) =
            __floats2half2_rn(oc[nt][0]*in0, oc[nt][1]*in0);
        *(__half2*)(out + (size_t)tok1*CC + col) =
            __floats2half2_rn(oc[nt][2]*in1, oc[nt][3]*in1);
    }
}

// ---------------- host orchestration ----------------
extern "C" void kernel_launch(void* const* d_in, const int* in_sizes, int n_in,
                              void* d_out, int out_size)
{
    const float* x       = (const float*)d_in[0];
    const float* rpb1    = (const float*)d_in[1];
    const float* qkv_w1  = (const float*)d_in[2];
    const float* qkv_b1  = (const float*)d_in[3];
    const float* proj_w1 = (const float*)d_in[4];
    const float* proj_b1 = (const float*)d_in[5];
    const float* rpb2    = (const float*)d_in[6];
    const float* qkv_w2  = (const float*)d_in[7];
    const float* qkv_b2  = (const float*)d_in[8];
    const float* proj_w2 = (const float*)d_in[9];
    const float* proj_b2 = (const float*)d_in[10];
    const float* g1  = (const float*)d_in[11];
    const float* be1 = (const float*)d_in[12];
    const float* g2  = (const float*)d_in[13];
    const float* be2 = (const float*)d_in[14];
    const float* g3  = (const float*)d_in[15];
    const float* be3 = (const float*)d_in[16];
    const float* g4  = (const float*)d_in[17];
    const float* be4 = (const float*)d_in[18];
    const float* m1w1 = (const float*)d_in[19];
    const float* m1b1 = (const float*)d_in[20];
    const float* m1w2 = (const float*)d_in[21];
    const float* m1b2 = (const float*)d_in[22];
    const float* m2w1 = (const float*)d_in[23];
    const float* m2b1 = (const float*)d_in[24];
    const float* m2w2 = (const float*)d_in[25];
    const float* m2b2 = (const float*)d_in[26];
    float* out = (float*)d_out;

    __half *xnh, *qkvh, *atth, *hidh, *wh;
    float *xb;
    cudaGetSymbolAddress((void**)&xnh,  g_xnh);
    cudaGetSymbolAddress((void**)&qkvh, g_qkvh);
    cudaGetSymbolAddress((void**)&atth, g_atth);
    cudaGetSymbolAddress((void**)&hidh, g_hidh);
    cudaGetSymbolAddress((void**)&xb,   g_x);
    cudaGetSymbolAddress((void**)&wh,   g_wh);

    cudaFuncSetAttribute(hgemm_kernel<0>,
        cudaFuncAttributeMaxDynamicSharedMemorySize, GSMEM_BYTES);
    cudaFuncSetAttribute(hgemm_kernel<1>,
        cudaFuncAttributeMaxDynamicSharedMemorySize, GSMEM_BYTES);
    cudaFuncSetAttribute(hgemm_kernel<2>,
        cudaFuncAttributeMaxDynamicSharedMemorySize, GSMEM_BYTES);

    // fused weight convert
    {
        CvtArgs a;
        const float* srcs[8] = {qkv_w1, proj_w1, m1w1, m1w2,
                                qkv_w2, proj_w2, m2w1, m2w2};
        const int offs[8] = {OFF_QKV1, OFF_PROJ1, OFF_M1W1, OFF_M1W2,
                             OFF_QKV2, OFF_PROJ2, OFF_M2W1, OFF_M2W2};
        const int ns[8] = {CC*QKV_N, CC*CC, CC*HID, HID*CC,
                           CC*QKV_N, CC*CC, CC*HID, HID*CC};
        int cum = 0;
        for (int i = 0; i < 8; i++) {
            a.src[i] = srcs[i];
            a.dstoff[i] = offs[i];
            a.cum[i] = cum;
            cum += ns[i] / 4;
        }
        a.cum[8] = cum;
        cvt8_kernel<<<(cum + 255)/256, 256>>>(a, wh);
    }

    const int M = NTOK;
    dim3 lnGrid(M / 8);
    dim3 attnGrid(NWIN, NHEAD);

    // persistent grids: ~294-296 CTAs per GEMM launch (2 per SM, 128 thr)
    dim3 gQKV (QKV_N/128, 49);
    dim3 gPROJ(CC/128,    148);
    dim3 gMLP1(HID/128,   74);
    dim3 gMLP2(CC/128,    148);

    // ---- block 1 ----
    ln_kernel<<<lnGrid, 256>>>(x, g1, be1, xnh);
    hgemm_kernel<0><<<gQKV, 128, GSMEM_BYTES>>>(M, QKV_N, CC, xnh, wh+OFF_QKV1, qkv_b1, nullptr, nullptr, qkvh);
    attn_kernel<false><<<attnGrid, 256>>>(qkvh, rpb1, atth);
    hgemm_kernel<2><<<gPROJ, 128, GSMEM_BYTES>>>(M, CC, CC, atth, wh+OFF_PROJ1, proj_b1, x, xb, nullptr);
    ln_kernel<<<lnGrid, 256>>>(xb, g2, be2, xnh);
    hgemm_kernel<1><<<gMLP1, 128, GSMEM_BYTES>>>(M, HID, CC, xnh, wh+OFF_M1W1, m1b1, nullptr, nullptr, hidh);
    hgemm_kernel<2><<<gMLP2, 128, GSMEM_BYTES>>>(M, CC, HID, hidh, wh+OFF_M1W2, m1b2, xb, xb, nullptr);

    // ---- block 2 (shifted) ----
    ln_kernel<<<lnGrid, 256>>>(xb, g3, be3, xnh);
    hgemm_kernel<0><<<gQKV, 128, GSMEM_BYTES>>>(M, QKV_N, CC, xnh, wh+OFF_QKV2, qkv_b2, nullptr, nullptr, qkvh);
    attn_kernel<true><<<attnGrid, 256>>>(qkvh, rpb2, atth);
    hgemm_kernel<2><<<gPROJ, 128, GSMEM_BYTES>>>(M, CC, CC, atth, wh+OFF_PROJ2, proj_b2, xb, xb, nullptr);
    ln_kernel<<<lnGrid, 256>>>(xb, g4, be4, xnh);
    hgemm_kernel<1><<<gMLP1, 128, GSMEM_BYTES>>>(M, HID, CC, xnh, wh+OFF_M2W1, m2b1, nullptr, nullptr, hidh);
    hgemm_kernel<2><<<gMLP2, 128, GSMEM_BYTES>>>(M, CC, HID, hidh, wh+OFF_M2W2, m2b2, xb, out, nullptr);
}